// round 16
// baseline (speedup 1.0000x reference)
#include <cuda_runtime.h>
#include <cuda_bf16.h>
#include <cooperative_groups.h>
#include <math.h>
#include <stdint.h>

namespace cg = cooperative_groups;
typedef __nv_bfloat16 bf16;

#define B_    8
#define T_    512
#define DIM_  512
#define R_    2048
#define BT_   4096
#define FFHP  1408   // FFH (1361) padded to multiple of 128; pads stay zero

// ---------------- device scratch (allocation-free rule) ----------------
__device__ float g_qWi [R_*DIM_];
__device__ bf16 g_bW1  [2*DIM_*R_];
__device__ bf16 g_bW2  [DIM_*2*DIM_];
__device__ bf16 g_bWqkv[3*DIM_*DIM_];
__device__ bf16 g_bWo  [DIM_*DIM_];
__device__ bf16 g_bWf1 [FFHP*DIM_];   // pad rows zero
__device__ bf16 g_bWf2p[DIM_*FFHP];   // pad cols zero
__device__ bf16 g_bWf3 [FFHP*DIM_];
__device__ unsigned g_pm[64*R_];
__device__ unsigned g_nm[64*R_];
__device__ float g_xp  [(size_t)BT_*R_];
__device__ float g_acts[(size_t)BT_*R_];
__device__ float g_y   [(size_t)BT_*DIM_];
__device__ float g_sc  [(size_t)64*T_*T_];
__device__ float g_xres[(size_t)BT_*DIM_];
__device__ float g_g   [(size_t)BT_*FFHP];
__device__ float g_red [9*256];
__device__ float g_thr [9];
// pre-split hi/lo activation pairs (bf16)
__device__ bf16 g_hnh[(size_t)BT_*R_],     g_hnl[(size_t)BT_*R_];
__device__ bf16 g_hh [(size_t)BT_*2*DIM_], g_hl2[(size_t)BT_*2*DIM_];
__device__ bf16 g_xah[(size_t)BT_*DIM_],   g_xal[(size_t)BT_*DIM_];
__device__ bf16 g_qkvh[(size_t)BT_*3*DIM_],g_qkvl[(size_t)BT_*3*DIM_];
__device__ bf16 g_sph[(size_t)64*T_*T_],   g_spl[(size_t)64*T_*T_];
__device__ bf16 g_vth[(size_t)64*64*T_],   g_vtl[(size_t)64*64*T_];
__device__ bf16 g_oh [(size_t)BT_*DIM_],   g_ol [(size_t)BT_*DIM_];
__device__ bf16 g_xfh[(size_t)BT_*DIM_],   g_xfl[(size_t)BT_*DIM_];
__device__ bf16 g_guh[(size_t)BT_*FFHP],   g_gul[(size_t)BT_*FFHP];

// ---------------- batched ternary quantization --------------------------
// Per-tensor reduction order bit-identical to R3..R15. Do not change.
struct Q9 {
    const float* src[9];
    float*       dstf[9];
    bf16*        dstb[9];
    int          n[9];
    int          srow[9];
    int          drow[9];
};

__global__ void absmean_partial_all(Q9 q, float* __restrict__ partial) {
    int y = blockIdx.y;
    const float* __restrict__ w = q.src[y];
    int n = q.n[y];
    __shared__ float sm[256];
    float acc = 0.f;
    int stride = gridDim.x * 256;
    for (int i = blockIdx.x * 256 + threadIdx.x; i < n; i += stride) acc += fabsf(w[i]);
    sm[threadIdx.x] = acc; __syncthreads();
    for (int s = 128; s > 0; s >>= 1) {
        if (threadIdx.x < s) sm[threadIdx.x] += sm[threadIdx.x + s];
        __syncthreads();
    }
    if (threadIdx.x == 0) partial[y * 256 + blockIdx.x] = sm[0];
}

__global__ void absmean_final_all(const float* __restrict__ partial, Q9 q,
                                  float* __restrict__ thr) {
    int y = blockIdx.x;
    __shared__ float sm[256];
    sm[threadIdx.x] = partial[y * 256 + threadIdx.x]; __syncthreads();
    for (int s = 128; s > 0; s >>= 1) {
        if (threadIdx.x < s) sm[threadIdx.x] += sm[threadIdx.x + s];
        __syncthreads();
    }
    if (threadIdx.x == 0) thr[y] = __fmul_rn(__fdiv_rn(sm[0], (float)q.n[y]), 0.7f);
}

__global__ void quantize_all(Q9 q, const float* __restrict__ thr) {
    int y = blockIdx.y;
    int i = blockIdx.x * 256 + threadIdx.x;
    if (i < q.n[y]) {
        float v = q.src[y][i], t = thr[y];
        float qq = (fabsf(v) > t) ? (v > 0.f ? 1.f : -1.f) : 0.f;
        float ov = __fadd_rn(v, __fsub_rn(qq, v));
        int j = i;
        if (q.srow[y] != q.drow[y]) j = (i / q.srow[y]) * q.drow[y] + (i % q.srow[y]);
        if (q.dstf[y]) q.dstf[y][j] = ov;
        if (q.dstb[y]) q.dstb[y][j] = __float2bfloat16(ov);
    }
}

__global__ void build_masks(const float* __restrict__ Wr, const float* __restrict__ thr,
                            unsigned* __restrict__ pm, unsigned* __restrict__ nm) {
    int r = blockIdx.x * 4 + (threadIdx.x >> 6);
    int w = threadIdx.x & 63;
    float t = thr[8];
    const float4* row = (const float4*)(Wr + (size_t)r * R_ + w * 32);
    unsigned p = 0u, ng = 0u;
    #pragma unroll
    for (int i4 = 0; i4 < 8; i4++) {
        float4 v4 = row[i4];
        float vv[4] = {v4.x, v4.y, v4.z, v4.w};
        #pragma unroll
        for (int j = 0; j < 4; j++) {
            float v = vv[j];
            if (fabsf(v) > t) {
                if (v > 0.f) p |= (1u << (i4 * 4 + j)); else ng |= (1u << (i4 * 4 + j));
            }
        }
    }
    pm[w * R_ + r] = p;
    nm[w * R_ + r] = ng;
}

// ---------------- epilogue -----------------------------------------------
template<int EPI>
__device__ __forceinline__ float epi_f(float v, const float* bias, const float* extra,
                                       int gm, int gn, int lde) {
    if (bias) v = __fadd_rn(v, bias[gn]);
    if (EPI == 1) v = 0.5f * v * (1.0f + erff(v * 0.70710678118654752f));
    else if (EPI == 2) v = v / (1.0f + expf(-v));
    else if (EPI == 3) v = v * extra[(size_t)gm * lde + gn];
    else if (EPI == 4) v = __fadd_rn(extra[(size_t)gm * lde + gn], v);
    return v;
}

// ---------------- mma.sync / cp.async helpers -----------------------------
__device__ __forceinline__ uint32_t smem_u32(const void* p) {
    uint32_t a;
    asm("{ .reg .u64 t; cvta.to.shared.u64 t, %1; cvt.u32.u64 %0, t; }" : "=r"(a) : "l"(p));
    return a;
}
__device__ __forceinline__ void ldm_x4(uint32_t& a0, uint32_t& a1, uint32_t& a2, uint32_t& a3,
                                       uint32_t addr) {
    asm volatile("ldmatrix.sync.aligned.m8n8.x4.shared.b16 {%0,%1,%2,%3}, [%4];"
                 : "=r"(a0), "=r"(a1), "=r"(a2), "=r"(a3) : "r"(addr));
}
__device__ __forceinline__ void ldm_x2(uint32_t& b0, uint32_t& b1, uint32_t addr) {
    asm volatile("ldmatrix.sync.aligned.m8n8.x2.shared.b16 {%0,%1}, [%2];"
                 : "=r"(b0), "=r"(b1) : "r"(addr));
}
__device__ __forceinline__ void mma_bf16(float* d, const uint32_t* a, const uint32_t* b) {
    asm volatile("mma.sync.aligned.m16n8k16.row.col.f32.bf16.bf16.f32 "
                 "{%0,%1,%2,%3}, {%4,%5,%6,%7}, {%8,%9}, {%0,%1,%2,%3};"
                 : "+f"(d[0]), "+f"(d[1]), "+f"(d[2]), "+f"(d[3])
                 : "r"(a[0]), "r"(a[1]), "r"(a[2]), "r"(a[3]), "r"(b[0]), "r"(b[1]));
}
__device__ __forceinline__ void cpa16(uint32_t dst, const void* src) {
    asm volatile("cp.async.cg.shared.global [%0], [%1], 16;" :: "r"(dst), "l"(src));
}
#define CPA_COMMIT() asm volatile("cp.async.commit_group;" ::: "memory")
#define CPA_WAIT1()  asm volatile("cp.async.wait_group 1;" ::: "memory")
#define CPA_WAIT0()  asm volatile("cp.async.wait_group 0;" ::: "memory")

#define PITCH 40    // bf16 per smem row (80B, 16B-aligned, ldmatrix conflict-free)
#define BUFB  10240 // bytes per operand buffer (128 rows * 80B)

// ---------------- HMMA GEMM, pre-split A, cp.async 2-stage (R14-proven) ---
template<int EPI, bool HLOUT>
__global__ void __launch_bounds__(256)
gemm_bb(const bf16* __restrict__ Ah, const bf16* __restrict__ Al,
        const bf16* __restrict__ Bb,
        const float* __restrict__ bias, const float* __restrict__ extra,
        float* __restrict__ C, bf16* __restrict__ Ch, bf16* __restrict__ Cl,
        int K, int lda, int ldb, int ldc, int lde)
{
    extern __shared__ __align__(16) char dsm[];
    const uint32_t sb = smem_u32(dsm);

    const int tid = threadIdx.x, wid = tid >> 5, lane = tid & 31;
    const int row0 = blockIdx.y * 128, col0 = blockIdx.x * 128;
    const int wm = (wid >> 2) * 64, wn = (wid & 3) * 32;
    const int lrow = tid >> 1, lhalf = tid & 1;
    const int NC = K >> 5;

    float acc[4][4][4];
    #pragma unroll
    for (int i = 0; i < 4; i++)
        #pragma unroll
        for (int j = 0; j < 4; j++)
            #pragma unroll
            for (int c = 0; c < 4; c++) acc[i][j][c] = 0.f;

    auto prefetch = [&](int c, int s) {
        int kt = c << 5;
        uint32_t doff = sb + s * (3 * BUFB) + (uint32_t)lrow * 80 + lhalf * 32;
        const bf16* ga = Ah + (size_t)(row0 + lrow) * lda + kt + lhalf * 16;
        const bf16* gl = Al + (size_t)(row0 + lrow) * lda + kt + lhalf * 16;
        const bf16* gb = Bb + (size_t)(col0 + lrow) * ldb + kt + lhalf * 16;
        cpa16(doff,                ga);     cpa16(doff + 16,            ga + 8);
        cpa16(doff + BUFB,         gl);     cpa16(doff + BUFB + 16,     gl + 8);
        cpa16(doff + 2 * BUFB,     gb);     cpa16(doff + 2 * BUFB + 16, gb + 8);
        CPA_COMMIT();
    };

    prefetch(0, 0);
    for (int c = 0; c < NC; c++) {
        if (c + 1 < NC) prefetch(c + 1, (c + 1) & 1);
        if (c + 1 < NC) CPA_WAIT1(); else CPA_WAIT0();
        __syncthreads();

        const uint32_t sAhi = sb + (c & 1) * (3 * BUFB);
        const uint32_t sAlo = sAhi + BUFB;
        const uint32_t sBs  = sAhi + 2 * BUFB;

        #pragma unroll
        for (int ks = 0; ks < 32; ks += 16) {
            uint32_t afh[4][4], afl[4][4], bf[4][2];
            int ar = lane & 15, ac = (lane >> 4) * 8;
            #pragma unroll
            for (int i = 0; i < 4; i++) {
                uint32_t off = (uint32_t)(wm + i * 16 + ar) * (PITCH * 2) + (ks + ac) * 2;
                ldm_x4(afh[i][0], afh[i][1], afh[i][2], afh[i][3], sAhi + off);
                ldm_x4(afl[i][0], afl[i][1], afl[i][2], afl[i][3], sAlo + off);
            }
            int br = lane & 7, bm = (lane >> 3) & 1;
            #pragma unroll
            for (int j = 0; j < 4; j++) {
                uint32_t off = (uint32_t)(wn + j * 8 + br) * (PITCH * 2) + (ks + bm * 8) * 2;
                ldm_x2(bf[j][0], bf[j][1], sBs + off);
            }
            #pragma unroll
            for (int i = 0; i < 4; i++)
                #pragma unroll
                for (int j = 0; j < 4; j++) {
                    mma_bf16(acc[i][j], afh[i], bf[j]);
                    mma_bf16(acc[i][j], afl[i], bf[j]);
                }
        }
        __syncthreads();
    }

    const int gr = lane >> 2, gc = (lane & 3) * 2;
    #pragma unroll
    for (int i = 0; i < 4; i++) {
        #pragma unroll
        for (int j = 0; j < 4; j++) {
            int gm0 = row0 + wm + i * 16 + gr;
            int gm1 = gm0 + 8;
            int gn  = col0 + wn + j * 8 + gc;
            float v00 = epi_f<EPI>(acc[i][j][0], bias, extra, gm0, gn,     lde);
            float v01 = epi_f<EPI>(acc[i][j][1], bias, extra, gm0, gn + 1, lde);
            float v10 = epi_f<EPI>(acc[i][j][2], bias, extra, gm1, gn,     lde);
            float v11 = epi_f<EPI>(acc[i][j][3], bias, extra, gm1, gn + 1, lde);
            if (HLOUT) {
                bf16 h;
                h = __float2bfloat16(v00); Ch[(size_t)gm0 * ldc + gn]     = h; Cl[(size_t)gm0 * ldc + gn]     = __float2bfloat16(v00 - __bfloat162float(h));
                h = __float2bfloat16(v01); Ch[(size_t)gm0 * ldc + gn + 1] = h; Cl[(size_t)gm0 * ldc + gn + 1] = __float2bfloat16(v01 - __bfloat162float(h));
                h = __float2bfloat16(v10); Ch[(size_t)gm1 * ldc + gn]     = h; Cl[(size_t)gm1 * ldc + gn]     = __float2bfloat16(v10 - __bfloat162float(h));
                h = __float2bfloat16(v11); Ch[(size_t)gm1 * ldc + gn + 1] = h; Cl[(size_t)gm1 * ldc + gn + 1] = __float2bfloat16(v11 - __bfloat162float(h));
            } else {
                C[(size_t)gm0 * ldc + gn]     = v00;
                C[(size_t)gm0 * ldc + gn + 1] = v01;
                C[(size_t)gm1 * ldc + gn]     = v10;
                C[(size_t)gm1 * ldc + gn + 1] = v11;
            }
        }
    }
}

// ---------------- attention scores on pre-split qkv: sc = (q k^T)/8 -------
__global__ void __launch_bounds__(256)
gemm_qk(const bf16* __restrict__ qh, const bf16* __restrict__ ql, float* __restrict__ sc)
{
    __shared__ __align__(16) bf16 Ahi[128 * PITCH];
    __shared__ __align__(16) bf16 Alo[128 * PITCH];
    __shared__ __align__(16) bf16 Bhi[128 * PITCH];
    __shared__ __align__(16) bf16 Blo[128 * PITCH];

    const int tid = threadIdx.x, wid = tid >> 5, lane = tid & 31;
    const int z = blockIdx.z;
    const size_t aoff = (size_t)(z >> 3) * T_ * 1536 + (z & 7) * 64;
    const size_t boff = aoff + 512;
    float* C = sc + (size_t)z * T_ * T_;
    const int row0 = blockIdx.y * 128, col0 = blockIdx.x * 128;
    const int wm = (wid >> 2) * 64, wn = (wid & 3) * 32;
    const uint32_t sAh = smem_u32(Ahi), sAl = smem_u32(Alo);
    const uint32_t sBh = smem_u32(Bhi), sBl = smem_u32(Blo);
    const int lrow = tid >> 1, lhalf = tid & 1;

    float acc[4][4][4];
    #pragma unroll
    for (int i = 0; i < 4; i++)
        #pragma unroll
        for (int j = 0; j < 4; j++)
            #pragma unroll
            for (int c = 0; c < 4; c++) acc[i][j][c] = 0.f;

    #pragma unroll
    for (int kt = 0; kt < 64; kt += 32) {
        {
            size_t ai = aoff + (size_t)(row0 + lrow) * 1536 + kt + lhalf * 16;
            size_t bi = boff + (size_t)(col0 + lrow) * 1536 + kt + lhalf * 16;
            uint4* d;
            d = (uint4*)(Ahi + lrow * PITCH + lhalf * 16);
            d[0] = ((const uint4*)(qh + ai))[0]; d[1] = ((const uint4*)(qh + ai))[1];
            d = (uint4*)(Alo + lrow * PITCH + lhalf * 16);
            d[0] = ((const uint4*)(ql + ai))[0]; d[1] = ((const uint4*)(ql + ai))[1];
            d = (uint4*)(Bhi + lrow * PITCH + lhalf * 16);
            d[0] = ((const uint4*)(qh + bi))[0]; d[1] = ((const uint4*)(qh + bi))[1];
            d = (uint4*)(Blo + lrow * PITCH + lhalf * 16);
            d[0] = ((const uint4*)(ql + bi))[0]; d[1] = ((const uint4*)(ql + bi))[1];
        }
        __syncthreads();
        #pragma unroll
        for (int ks = 0; ks < 32; ks += 16) {
            uint32_t afh[4][4], afl[4][4], bfh[4][2], bfl[4][2];
            int ar = lane & 15, ac = (lane >> 4) * 8;
            #pragma unroll
            for (int i = 0; i < 4; i++) {
                uint32_t off = (uint32_t)(wm + i * 16 + ar) * (PITCH * 2) + (ks + ac) * 2;
                ldm_x4(afh[i][0], afh[i][1], afh[i][2], afh[i][3], sAh + off);
                ldm_x4(afl[i][0], afl[i][1], afl[i][2], afl[i][3], sAl + off);
            }
            int br = lane & 7, bm = (lane >> 3) & 1;
            #pragma unroll
            for (int j = 0; j < 4; j++) {
                uint32_t off = (uint32_t)(wn + j * 8 + br) * (PITCH * 2) + (ks + bm * 8) * 2;
                ldm_x2(bfh[j][0], bfh[j][1], sBh + off);
                ldm_x2(bfl[j][0], bfl[j][1], sBl + off);
            }
            #pragma unroll
            for (int i = 0; i < 4; i++)
                #pragma unroll
                for (int j = 0; j < 4; j++) {
                    mma_bf16(acc[i][j], afh[i], bfh[j]);
                    mma_bf16(acc[i][j], afh[i], bfl[j]);
                    mma_bf16(acc[i][j], afl[i], bfh[j]);
                }
        }
        __syncthreads();
    }

    const int gr = lane >> 2, gc = (lane & 3) * 2;
    #pragma unroll
    for (int i = 0; i < 4; i++) {
        #pragma unroll
        for (int j = 0; j < 4; j++) {
            int gm0 = row0 + wm + i * 16 + gr;
            int gm1 = gm0 + 8;
            int gn  = col0 + wn + j * 8 + gc;
            C[(size_t)gm0 * T_ + gn]     = acc[i][j][0] * 0.125f;
            C[(size_t)gm0 * T_ + gn + 1] = acc[i][j][1] * 0.125f;
            C[(size_t)gm1 * T_ + gn]     = acc[i][j][2] * 0.125f;
            C[(size_t)gm1 * T_ + gn + 1] = acc[i][j][3] * 0.125f;
        }
    }
}

// ---------------- v transpose on pre-split qkv: vt[z][d][t] ---------------
__global__ void transpose_v(const bf16* __restrict__ qh, const bf16* __restrict__ ql,
                            bf16* __restrict__ vth, bf16* __restrict__ vtl) {
    __shared__ uint32_t tile[32][33];
    const int z = blockIdx.z;
    const size_t s = (size_t)(z >> 3) * T_ * 1536 + 1024 + (z & 7) * 64;
    const int tbase = blockIdx.x * 32, dbase = blockIdx.y * 32;
    const int tx = threadIdx.x & 31, ty = threadIdx.x >> 5;
    #pragma unroll
    for (int l = 0; l < 4; l++) {
        size_t ix = s + (size_t)(tbase + ty + l * 8) * 1536 + dbase + tx;
        tile[tx][ty + l * 8] = (uint32_t)__bfloat16_as_ushort(qh[ix]) |
                               ((uint32_t)__bfloat16_as_ushort(ql[ix]) << 16);
    }
    __syncthreads();
    #pragma unroll
    for (int l = 0; l < 4; l++) {
        size_t ox = (size_t)z * 64 * T_ + (size_t)(dbase + ty + l * 8) * T_ + tbase + tx;
        uint32_t v = tile[ty + l * 8][tx];
        vth[ox] = __ushort_as_bfloat16((unsigned short)(v & 0xFFFF));
        vtl[ox] = __ushort_as_bfloat16((unsigned short)(v >> 16));
    }
}

// ---------------- attention output on pre-split: o = attn @ v (hl out) ----
__global__ void __launch_bounds__(256)
gemm_ov(const bf16* __restrict__ ph, const bf16* __restrict__ pl,
        const bf16* __restrict__ vth, const bf16* __restrict__ vtl,
        bf16* __restrict__ oh, bf16* __restrict__ ol)
{
    __shared__ __align__(16) bf16 Ahi[128 * PITCH];
    __shared__ __align__(16) bf16 Alo[128 * PITCH];
    __shared__ __align__(16) bf16 Bhi[64 * PITCH];
    __shared__ __align__(16) bf16 Blo[64 * PITCH];

    const int tid = threadIdx.x, wid = tid >> 5, lane = tid & 31;
    const int z = blockIdx.y;
    const bf16* Ahp = ph + (size_t)z * T_ * T_;
    const bf16* Alp = pl + (size_t)z * T_ * T_;
    const bf16* Bhp = vth + (size_t)z * 64 * T_;
    const bf16* Blp = vtl + (size_t)z * 64 * T_;
    const size_t coff = (size_t)(z >> 3) * T_ * DIM_ + (z & 7) * 64;
    const int row0 = blockIdx.x * 128;
    const int wm = (wid >> 2) * 64, wn = (wid & 3) * 16;
    const uint32_t sAh = smem_u32(Ahi), sAl = smem_u32(Alo);
    const uint32_t sBh = smem_u32(Bhi), sBl = smem_u32(Blo);
    const int lrow = tid >> 1, lhalf = tid & 1;

    float acc[4][2][4];
    #pragma unroll
    for (int i = 0; i < 4; i++)
        #pragma unroll
        for (int j = 0; j < 2; j++)
            #pragma unroll
            for (int c = 0; c < 4; c++) acc[i][j][c] = 0.f;

    for (int kt = 0; kt < T_; kt += 32) {
        {
            size_t ai = (size_t)(row0 + lrow) * T_ + kt + lhalf * 16;
            uint4* d;
            d = (uint4*)(Ahi + lrow * PITCH + lhalf * 16);
            d[0] = ((const uint4*)(Ahp + ai))[0]; d[1] = ((const uint4*)(Ahp + ai))[1];
            d = (uint4*)(Alo + lrow * PITCH + lhalf * 16);
            d[0] = ((const uint4*)(Alp + ai))[0]; d[1] = ((const uint4*)(Alp + ai))[1];
            if (tid < 128) {
                size_t bi = (size_t)lrow * T_ + kt + lhalf * 16;
                d = (uint4*)(Bhi + lrow * PITCH + lhalf * 16);
                d[0] = ((const uint4*)(Bhp + bi))[0]; d[1] = ((const uint4*)(Bhp + bi))[1];
                d = (uint4*)(Blo + lrow * PITCH + lhalf * 16);
                d[0] = ((const uint4*)(Blp + bi))[0]; d[1] = ((const uint4*)(Blp + bi))[1];
            }
        }
        __syncthreads();
        #pragma unroll
        for (int ks = 0; ks < 32; ks += 16) {
            uint32_t afh[4][4], afl[4][4], bfh[2][2], bfl[2][2];
            int ar = lane & 15, ac = (lane >> 4) * 8;
            #pragma unroll
            for (int i = 0; i < 4; i++) {
                uint32_t off = (uint32_t)(wm + i * 16 + ar) * (PITCH * 2) + (ks + ac) * 2;
                ldm_x4(afh[i][0], afh[i][1], afh[i][2], afh[i][3], sAh + off);
                ldm_x4(afl[i][0], afl[i][1], afl[i][2], afl[i][3], sAl + off);
            }
            int br = lane & 7, bm = (lane >> 3) & 1;
            #pragma unroll
            for (int j = 0; j < 2; j++) {
                uint32_t off = (uint32_t)(wn + j * 8 + br) * (PITCH * 2) + (ks + bm * 8) * 2;
                ldm_x2(bfh[j][0], bfh[j][1], sBh + off);
                ldm_x2(bfl[j][0], bfl[j][1], sBl + off);
            }
            #pragma unroll
            for (int i = 0; i < 4; i++)
                #pragma unroll
                for (int j = 0; j < 2; j++) {
                    mma_bf16(acc[i][j], afh[i], bfh[j]);
                    mma_bf16(acc[i][j], afh[i], bfl[j]);
                    mma_bf16(acc[i][j], afl[i], bfh[j]);
                }
        }
        __syncthreads();
    }

    const int gr = lane >> 2, gc = (lane & 3) * 2;
    #pragma unroll
    for (int i = 0; i < 4; i++) {
        #pragma unroll
        for (int j = 0; j < 2; j++) {
            int gm0 = row0 + wm + i * 16 + gr;
            int gm1 = gm0 + 8;
            int gn  = wn + j * 8 + gc;
            float v; bf16 h;
            v = acc[i][j][0]; h = __float2bfloat16(v);
            oh[coff + (size_t)gm0 * DIM_ + gn] = h;     ol[coff + (size_t)gm0 * DIM_ + gn] = __float2bfloat16(v - __bfloat162float(h));
            v = acc[i][j][1]; h = __float2bfloat16(v);
            oh[coff + (size_t)gm0 * DIM_ + gn + 1] = h; ol[coff + (size_t)gm0 * DIM_ + gn + 1] = __float2bfloat16(v - __bfloat162float(h));
            v = acc[i][j][2]; h = __float2bfloat16(v);
            oh[coff + (size_t)gm1 * DIM_ + gn] = h;     ol[coff + (size_t)gm1 * DIM_ + gn] = __float2bfloat16(v - __bfloat162float(h));
            v = acc[i][j][3]; h = __float2bfloat16(v);
            oh[coff + (size_t)gm1 * DIM_ + gn + 1] = h; ol[coff + (size_t)gm1 * DIM_ + gn + 1] = __float2bfloat16(v - __bfloat162float(h));
        }
    }
}

// ---------------- FAST fp32 SGEMM (xp only; bit-exact, unchanged) --------
template<int EPI, bool TB>
__global__ void __launch_bounds__(256)
gemm_fast(const float* __restrict__ A, const float* __restrict__ Bm,
          const float* __restrict__ bias, const float* __restrict__ extra,
          float* __restrict__ C,
          int M, int N, int K, int lda, int ldb, int ldc, int lde,
          long aZ1, long aZ2, long bZ1, long bZ2, long cZ1, long cZ2,
          int zInner, float alpha)
{
    int z = blockIdx.z;
    int zo = z / zInner, zi = z - zo * zInner;
    A  += zo * aZ1 + zi * aZ2;
    Bm += zo * bZ1 + zi * bZ2;
    C  += zo * cZ1 + zi * cZ2;

    __shared__ float As[16][132];
    __shared__ float Bs[16][132];
    const int tid = threadIdx.x;
    const int row0 = blockIdx.y * 128, col0 = blockIdx.x * 128;
    const int ty = tid >> 4, tx = tid & 15;
    const int KT = K >> 4;

    const int am = (tid >> 2), ak = (tid & 3) << 2;
    const int bk = (tid >> 5), bn = (tid & 31) << 2;

    float4 ra[2], rb[2];
    float acc[8][8];
    #pragma unroll
    for (int i = 0; i < 8; i++)
        #pragma unroll
        for (int j = 0; j < 8; j++) acc[i][j] = 0.f;

    auto ldg = [&](int kt0) {
        #pragma unroll
        for (int l = 0; l < 2; l++)
            ra[l] = *(const float4*)(A + (size_t)(row0 + am + l * 64) * lda + kt0 + ak);
        if (TB) {
            #pragma unroll
            for (int l = 0; l < 2; l++)
                rb[l] = *(const float4*)(Bm + (size_t)(col0 + am + l * 64) * ldb + kt0 + ak);
        } else {
            #pragma unroll
            for (int l = 0; l < 2; l++)
                rb[l] = *(const float4*)(Bm + (size_t)(kt0 + bk + l * 8) * ldb + col0 + bn);
        }
    };
    auto sts = [&]() {
        #pragma unroll
        for (int l = 0; l < 2; l++) {
            As[ak + 0][am + l * 64] = ra[l].x;
            As[ak + 1][am + l * 64] = ra[l].y;
            As[ak + 2][am + l * 64] = ra[l].z;
            As[ak + 3][am + l * 64] = ra[l].w;
        }
        if (TB) {
            #pragma unroll
            for (int l = 0; l < 2; l++) {
                Bs[ak + 0][am + l * 64] = rb[l].x;
                Bs[ak + 1][am + l * 64] = rb[l].y;
                Bs[ak + 2][am + l * 64] = rb[l].z;
                Bs[ak + 3][am + l * 64] = rb[l].w;
            }
        } else {
            #pragma unroll
            for (int l = 0; l < 2; l++)
                *(float4*)&Bs[bk + l * 8][bn] = rb[l];
        }
    };

    ldg(0); sts(); __syncthreads();
    for (int kt = 1; kt <= KT; kt++) {
        if (kt < KT) ldg(kt << 4);
        #pragma unroll
        for (int k = 0; k < 16; k++) {
            float4 a0 = *(const float4*)&As[k][ty * 8];
            float4 a1 = *(const float4*)&As[k][ty * 8 + 4];
            float4 b0 = *(const float4*)&Bs[k][tx * 8];
            float4 b1 = *(const float4*)&Bs[k][tx * 8 + 4];
            float av[8] = {a0.x, a0.y, a0.z, a0.w, a1.x, a1.y, a1.z, a1.w};
            float bv[8] = {b0.x, b0.y, b0.z, b0.w, b1.x, b1.y, b1.z, b1.w};
            #pragma unroll
            for (int i = 0; i < 8; i++)
                #pragma unroll
                for (int j = 0; j < 8; j++) acc[i][j] += av[i] * bv[j];
        }
        __syncthreads();
        if (kt < KT) { sts(); __syncthreads(); }
    }

    #pragma unroll
    for (int i = 0; i < 8; i++) {
        int gm = row0 + ty * 8 + i;
        #pragma unroll
        for (int j = 0; j < 8; j++) {
            int gn = col0 + tx * 8 + j;
            float v = epi_f<EPI>(acc[i][j] * alpha, bias, extra, gm, gn, lde);
            C[(size_t)gm * ldc + gn] = v;
        }
    }
}

// ---------------- LIF scan: parallel remote stores + arrive/wait split ----
__global__ void __cluster_dims__(8, 1, 1) __launch_bounds__(256, 1)
scan_kernel(const float* __restrict__ xp,
            const float* __restrict__ beta, const float* __restrict__ sfa_inc,
            const float* __restrict__ sfa_decay,
            const unsigned* __restrict__ pmask, const unsigned* __restrict__ nmask,
            float* __restrict__ acts)
{
    cg::cluster_group cl = cg::this_cluster();
    int crank = (int)cl.block_rank();
    int b = blockIdx.x >> 3;
    int tid = threadIdx.x;
    int r = crank * 256 + tid;
    int lane = tid & 31;
    int gw = r >> 5;

    __shared__ unsigned s_spk[2][64];
    if (tid < 64) { s_spk[0][tid] = 0u; s_spk[1][tid] = 0u; }

    unsigned pm[64], nm[64];
    #pragma unroll
    for (int w = 0; w < 64; w++) { pm[w] = pmask[w * R_ + r]; nm[w] = nmask[w * R_ + r]; }

    float beta_r = beta[r], dec = sfa_decay[r], inc = sfa_inc[r];
    float mem = 0.f, ath = 0.f;
    const float* __restrict__ xrow = xp + (size_t)b * T_ * R_ + r;
    float* __restrict__ arow = acts + (size_t)b * T_ * R_ + r;

    cl.sync();

    float xcur = xrow[0];
    for (int t = 0; t < T_; t++) {
        int pb = t & 1, wb = pb ^ 1;
        int acc = 0;
        #pragma unroll
        for (int w = 0; w < 64; w++) {
            unsigned s = s_spk[pb][w];
            acc += __popc(pm[w] & s);
            acc -= __popc(nm[w] & s);
        }
        float cur = __fadd_rn(xcur, (float)acc);
        mem = __fadd_rn(__fmul_rn(beta_r, mem), cur);
        float th = __fadd_rn(1.0f, ath);
        bool sp = __fsub_rn(mem, th) > 0.0f;
        float spk = sp ? 1.0f : 0.0f;
        if (sp) mem = 0.0f;
        ath = __fadd_rn(__fmul_rn(dec, ath), __fmul_rn(inc, spk));
        arow[(size_t)t * R_] = spk;

        // parallel remote ballot broadcast: lanes 0..7 each store to one rank
        unsigned bal = __ballot_sync(0xffffffffu, sp);
        if (lane < 8) {
            unsigned* rp = (unsigned*)cl.map_shared_rank(&s_spk[wb][gw], lane);
            *rp = bal;
        }
        // split barrier: arrive, prefetch next input, then wait
        asm volatile("barrier.cluster.arrive.aligned;" ::: "memory");
        if (t + 1 < T_) xcur = xrow[(size_t)(t + 1) * R_];
        asm volatile("barrier.cluster.wait.aligned;" ::: "memory");
    }
}

// ---------------- rmsnorm -> pre-split hi/lo ------------------------------
__global__ void rmsnorm_hl(const float* __restrict__ x, const float* __restrict__ w,
                           bf16* __restrict__ oh, bf16* __restrict__ ol, int N) {
    int row = blockIdx.x;
    const float* xr = x + (size_t)row * N;
    __shared__ float sm[256];
    __shared__ float s_scale;
    float acc = 0.f;
    for (int i = threadIdx.x; i < N; i += 256) { float v = xr[i]; acc += v * v; }
    sm[threadIdx.x] = acc; __syncthreads();
    for (int s = 128; s > 0; s >>= 1) {
        if (threadIdx.x < s) sm[threadIdx.x] += sm[threadIdx.x + s];
        __syncthreads();
    }
    if (threadIdx.x == 0)
        s_scale = rsqrtf(__fadd_rn(__fdiv_rn(sm[0], (float)N), 1e-6f));
    __syncthreads();
    float sc = s_scale;
    for (int i = threadIdx.x; i < N; i += 256) {
        float v = __fmul_rn(__fmul_rn(xr[i], sc), w[i]);
        size_t ix = (size_t)row * N + i;
        bf16 h = __float2bfloat16(v);
        oh[ix] = h;
        ol[ix] = __float2bfloat16(v - __bfloat162float(h));
    }
}

// ---------------- softmax -> pre-split probs ------------------------------
__global__ void softmax_k(const float* __restrict__ s, bf16* __restrict__ ph,
                          bf16* __restrict__ pl) {
    int row = blockIdx.x;
    const float* p = s + (size_t)row * 512;
    __shared__ float sm[128];
    int tid = threadIdx.x;
    float m = -3.402823466e38f;
    #pragma unroll
    for (int l = 0; l < 4; l++) m = fmaxf(m, p[tid + l * 128]);
    sm[tid] = m; __syncthreads();
    for (int st = 64; st > 0; st >>= 1) {
        if (tid < st) sm[tid] = fmaxf(sm[tid], sm[tid + st]);
        __syncthreads();
    }
    float M = sm[0]; __syncthreads();
    float e[4]; float acc = 0.f;
    #pragma unroll
    for (int l = 0; l < 4; l++) { e[l] = expf(p[tid + l * 128] - M); acc += e[l]; }
    sm[tid] = acc; __syncthreads();
    for (int st = 64; st > 0; st >>= 1) {
        if (tid < st) sm[tid] += sm[tid + st];
        __syncthreads();
    }
    float sum = sm[0];
    #pragma unroll
    for (int l = 0; l < 4; l++) {
        float v = __fdiv_rn(e[l], sum);
        size_t ix = (size_t)row * 512 + tid + l * 128;
        bf16 h = __float2bfloat16(v);
        ph[ix] = h;
        pl[ix] = __float2bfloat16(v - __bfloat162float(h));
    }
}

// ---------------- host ---------------------------------------------------
template<typename T> static T* devptr(const void* sym) {
    void* p = nullptr; cudaGetSymbolAddress(&p, sym); return (T*)p;
}

#define GB_SMEM (6 * BUFB)   // 61440 bytes, 2-stage (R14-proven)

template<int EPI>
static void GB(const bf16* Ah, const bf16* Al, const bf16* Bb, const float* bias,
               const float* extra, float* C,
               int M, int N, int K, int lda, int ldb, int ldc, int lde) {
    cudaFuncSetAttribute(gemm_bb<EPI, false>, cudaFuncAttributeMaxDynamicSharedMemorySize, GB_SMEM);
    dim3 grid(N / 128, M / 128);
    gemm_bb<EPI, false><<<grid, 256, GB_SMEM>>>(Ah, Al, Bb, bias, extra, C, nullptr, nullptr,
                                                K, lda, ldb, ldc, lde);
}

template<int EPI>
static void GBH(const bf16* Ah, const bf16* Al, const bf16* Bb, const float* bias,
                const float* extra, bf16* Ch, bf16* Cl,
                int M, int N, int K, int lda, int ldb, int ldc, int lde) {
    cudaFuncSetAttribute(gemm_bb<EPI, true>, cudaFuncAttributeMaxDynamicSharedMemorySize, GB_SMEM);
    dim3 grid(N / 128, M / 128);
    gemm_bb<EPI, true><<<grid, 256, GB_SMEM>>>(Ah, Al, Bb, bias, extra, nullptr, Ch, Cl,
                                               K, lda, ldb, ldc, lde);
}

template<int EPI, bool TB>
static void GF(const float* A, const float* Bm, const float* bias, const float* extra, float* C,
               int M, int N, int K, int lda, int ldb, int ldc, int lde,
               long aZ1, long aZ2, long bZ1, long bZ2, long cZ1, long cZ2,
               int zInner, int Z, float alpha) {
    dim3 grid(N / 128, M / 128, Z);
    gemm_fast<EPI, TB><<<grid, 256>>>(A, Bm, bias, extra, C, M, N, K, lda, ldb, ldc, lde,
                                      aZ1, aZ2, bZ1, bZ2, cZ1, cZ2, zInner, alpha);
}

extern "C" void kernel_launch(void* const* d_in, const int* in_sizes, int n_in,
                              void* d_out, int out_size) {
    const float* x        = (const float*)d_in[0];
    const float* Wi       = (const float*)d_in[1];
    const float* bi       = (const float*)d_in[2];
    const float* Wr       = (const float*)d_in[3];
    const float* rn_w     = (const float*)d_in[4];
    const float* W1       = (const float*)d_in[5];
    const float* b1       = (const float*)d_in[6];
    const float* W2       = (const float*)d_in[7];
    const float* b2       = (const float*)d_in[8];
    const float* anorm_w  = (const float*)d_in[9];
    const float* Wqkv     = (const float*)d_in[10];
    const float* Wo       = (const float*)d_in[11];
    const float* fnorm_w  = (const float*)d_in[12];
    const float* Wf1      = (const float*)d_in[13];
    const float* Wf2      = (const float*)d_in[14];
    const float* Wf3      = (const float*)d_in[15];
    const float* beta     = (const float*)d_in[16];
    const float* sfa_inc  = (const float*)d_in[17];
    const float* sfa_dec  = (const float*)d_in[18];
    float* out = (float*)d_out;
    const int FFH = in_sizes[13] / DIM_;

    float* red    = devptr<float>(g_red);
    float* thr    = devptr<float>(g_thr);
    float* qWi    = devptr<float>(g_qWi);
    bf16* bW1   = devptr<bf16>(g_bW1);
    bf16* bW2   = devptr<bf16>(g_bW2);
    bf16* bWqkv = devptr<bf16>(g_bWqkv);
    bf16* bWo   = devptr<bf16>(g_bWo);
    bf16* bWf1  = devptr<bf16>(g_bWf1);
    bf16* bWf2p = devptr<bf16>(g_bWf2p);
    bf16* bWf3  = devptr<bf16>(g_bWf3);
    unsigned* pm  = devptr<unsigned>(g_pm);
    unsigned* nm  = devptr<unsigned>(g_nm);
    float* xp     = devptr<float>(g_xp);
    float* acts   = devptr<float>(g_acts);
    float* y      = devptr<float>(g_y);
    float* sc     = devptr<float>(g_sc);
    float* xres   = devptr<float>(g_xres);
    float* gbuf   = devptr<float>(g_g);
    bf16 *hnh = devptr<bf16>(g_hnh), *hnl = devptr<bf16>(g_hnl);
    bf16 *hh  = devptr<bf16>(g_hh),  *hl  = devptr<bf16>(g_hl2);
    bf16 *xah = devptr<bf16>(g_xah), *xal = devptr<bf16>(g_xal);
    bf16 *qkvh= devptr<bf16>(g_qkvh),*qkvl= devptr<bf16>(g_qkvl);
    bf16 *sph = devptr<bf16>(g_sph), *spl = devptr<bf16>(g_spl);
    bf16 *vth = devptr<bf16>(g_vth), *vtl = devptr<bf16>(g_vtl);
    bf16 *oh  = devptr<bf16>(g_oh),  *ol  = devptr<bf16>(g_ol);
    bf16 *xfh = devptr<bf16>(g_xfh), *xfl = devptr<bf16>(g_xfl);
    bf16 *guh = devptr<bf16>(g_guh), *gul = devptr<bf16>(g_gul);

    // batched quantization (bit-identical per-tensor reduction order)
    Q9 q;
    for (int i = 0; i < 9; i++) { q.dstf[i] = nullptr; q.dstb[i] = nullptr; q.srow[i] = 1; q.drow[i] = 1; }
    q.src[0] = Wi;   q.dstf[0] = qWi;   q.n[0] = R_ * DIM_;
    q.src[1] = W1;   q.dstb[1] = bW1;   q.n[1] = 2 * DIM_ * R_;
    q.src[2] = W2;   q.dstb[2] = bW2;   q.n[2] = DIM_ * 2 * DIM_;
    q.src[3] = Wqkv; q.dstb[3] = bWqkv; q.n[3] = 3 * DIM_ * DIM_;
    q.src[4] = Wo;   q.dstb[4] = bWo;   q.n[4] = DIM_ * DIM_;
    q.src[5] = Wf1;  q.dstb[5] = bWf1;  q.n[5] = FFH * DIM_;
    q.src[6] = Wf2;  q.dstb[6] = bWf2p; q.n[6] = DIM_ * FFH;  q.srow[6] = FFH; q.drow[6] = FFHP;
    q.src[7] = Wf3;  q.dstb[7] = bWf3;  q.n[7] = FFH * DIM_;
    q.src[8] = Wr;   q.n[8] = R_ * R_;

    absmean_partial_all<<<dim3(256, 9), 256>>>(q, red);
    absmean_final_all<<<9, 256>>>(red, q, thr);
    quantize_all<<<dim3((2 * DIM_ * R_ + 255) / 256, 8), 256>>>(q, thr);
    build_masks<<<R_ / 4, 256>>>(Wr, thr, pm, nm);

    // xp = x @ qWi^T + bi  (fp32 exact — feeds the chaotic spike threshold)
    GF<0, true>(x, qWi, bi, nullptr, xp, BT_, R_, DIM_, DIM_, DIM_, R_, 0,
                0, 0, 0, 0, 0, 0, 1, 1, 1.f);

    // LIF scan
    scan_kernel<<<64, 256>>>(xp, beta, sfa_inc, sfa_dec, pm, nm, acts);

    // readout MLP (pre-split HMMA + cp.async 2-stage pipeline)
    rmsnorm_hl<<<BT_, 256>>>(acts, rn_w, hnh, hnl, R_);
    GBH<1>(hnh, hnl, bW1, b1, nullptr, hh, hl, BT_, 2 * DIM_, R_, R_, R_, 2 * DIM_, 0);
    GB<0>(hh, hl, bW2, b2, nullptr, y, BT_, DIM_, 2 * DIM_, 2 * DIM_, 2 * DIM_, DIM_, 0);

    // attention block
    rmsnorm_hl<<<BT_, 256>>>(y, anorm_w, xah, xal, DIM_);
    GBH<0>(xah, xal, bWqkv, nullptr, nullptr, qkvh, qkvl, BT_, 3 * DIM_, DIM_, DIM_, DIM_, 3 * DIM_, 0);
    gemm_qk<<<dim3(4, 4, 64), 256>>>(qkvh, qkvl, sc);
    softmax_k<<<64 * T_, 128>>>(sc, sph, spl);
    transpose_v<<<dim3(16, 2, 64), 256>>>(qkvh, qkvl, vth, vtl);
    gemm_ov<<<dim3(4, 64), 256>>>(sph, spl, vth, vtl, oh, ol);
    // x_res = y + o @ Wo^T
    GB<4>(oh, ol, bWo, nullptr, y, xres, BT_, DIM_, DIM_, DIM_, DIM_, DIM_, DIM_);

    // SwiGLU FFN (padded to FFHP=1408, pads exact zero)
    rmsnorm_hl<<<BT_, 256>>>(xres, fnorm_w, xfh, xfl, DIM_);
    GB<2>(xfh, xfl, bWf1, nullptr, nullptr, gbuf, BT_, FFHP, DIM_, DIM_, DIM_, FFHP, 0);
    GBH<3>(xfh, xfl, bWf3, nullptr, gbuf, guh, gul, BT_, FFHP, DIM_, DIM_, DIM_, FFHP, FFHP);
    GB<4>(guh, gul, bWf2p, nullptr, xres, out, BT_, DIM_, FFHP, FFHP, FFHP, DIM_, DIM_);
}

// round 17
// speedup vs baseline: 1.0576x; 1.0576x over previous
#include <cuda_runtime.h>
#include <cuda_bf16.h>
#include <cooperative_groups.h>
#include <math.h>
#include <stdint.h>

namespace cg = cooperative_groups;
typedef __nv_bfloat16 bf16;

#define B_    8
#define T_    512
#define DIM_  512
#define R_    2048
#define BT_   4096
#define FFHP  1408   // FFH (1361) padded to multiple of 128; pads stay zero

// ---------------- device scratch (allocation-free rule) ----------------
__device__ float g_qWi [R_*DIM_];
__device__ bf16 g_bW1  [2*DIM_*R_];
__device__ bf16 g_bW2  [DIM_*2*DIM_];
__device__ bf16 g_bWqkv[3*DIM_*DIM_];
__device__ bf16 g_bWo  [DIM_*DIM_];
__device__ bf16 g_bWf1 [FFHP*DIM_];   // pad rows zero
__device__ bf16 g_bWf2p[DIM_*FFHP];   // pad cols zero
__device__ bf16 g_bWf3 [FFHP*DIM_];
__device__ unsigned g_pm[64*R_];
__device__ unsigned g_nm[64*R_];
__device__ float g_xp  [(size_t)BT_*R_];
__device__ float g_acts[(size_t)BT_*R_];
__device__ float g_y   [(size_t)BT_*DIM_];
__device__ float g_sc  [(size_t)64*T_*T_];
__device__ float g_xres[(size_t)BT_*DIM_];
__device__ float g_g   [(size_t)BT_*FFHP];
__device__ float g_red [9*256];
__device__ float g_thr [9];
// pre-split hi/lo activation pairs (bf16)
__device__ bf16 g_hnh[(size_t)BT_*R_],     g_hnl[(size_t)BT_*R_];
__device__ bf16 g_hh [(size_t)BT_*2*DIM_], g_hl2[(size_t)BT_*2*DIM_];
__device__ bf16 g_xah[(size_t)BT_*DIM_],   g_xal[(size_t)BT_*DIM_];
__device__ bf16 g_qkvh[(size_t)BT_*3*DIM_],g_qkvl[(size_t)BT_*3*DIM_];
__device__ bf16 g_sph[(size_t)64*T_*T_],   g_spl[(size_t)64*T_*T_];
__device__ bf16 g_vth[(size_t)64*64*T_],   g_vtl[(size_t)64*64*T_];
__device__ bf16 g_oh [(size_t)BT_*DIM_],   g_ol [(size_t)BT_*DIM_];
__device__ bf16 g_xfh[(size_t)BT_*DIM_],   g_xfl[(size_t)BT_*DIM_];
__device__ bf16 g_guh[(size_t)BT_*FFHP],   g_gul[(size_t)BT_*FFHP];

// ---------------- batched ternary quantization --------------------------
// Per-tensor reduction order bit-identical to R3..R14. Do not change.
struct Q9 {
    const float* src[9];
    float*       dstf[9];
    bf16*        dstb[9];
    int          n[9];
    int          srow[9];
    int          drow[9];
};

__global__ void absmean_partial_all(Q9 q, float* __restrict__ partial) {
    int y = blockIdx.y;
    const float* __restrict__ w = q.src[y];
    int n = q.n[y];
    __shared__ float sm[256];
    float acc = 0.f;
    int stride = gridDim.x * 256;
    for (int i = blockIdx.x * 256 + threadIdx.x; i < n; i += stride) acc += fabsf(w[i]);
    sm[threadIdx.x] = acc; __syncthreads();
    for (int s = 128; s > 0; s >>= 1) {
        if (threadIdx.x < s) sm[threadIdx.x] += sm[threadIdx.x + s];
        __syncthreads();
    }
    if (threadIdx.x == 0) partial[y * 256 + blockIdx.x] = sm[0];
}

__global__ void absmean_final_all(const float* __restrict__ partial, Q9 q,
                                  float* __restrict__ thr) {
    int y = blockIdx.x;
    __shared__ float sm[256];
    sm[threadIdx.x] = partial[y * 256 + threadIdx.x]; __syncthreads();
    for (int s = 128; s > 0; s >>= 1) {
        if (threadIdx.x < s) sm[threadIdx.x] += sm[threadIdx.x + s];
        __syncthreads();
    }
    if (threadIdx.x == 0) thr[y] = __fmul_rn(__fdiv_rn(sm[0], (float)q.n[y]), 0.7f);
}

__global__ void quantize_all(Q9 q, const float* __restrict__ thr) {
    int y = blockIdx.y;
    int i = blockIdx.x * 256 + threadIdx.x;
    if (i < q.n[y]) {
        float v = q.src[y][i], t = thr[y];
        float qq = (fabsf(v) > t) ? (v > 0.f ? 1.f : -1.f) : 0.f;
        float ov = __fadd_rn(v, __fsub_rn(qq, v));
        int j = i;
        if (q.srow[y] != q.drow[y]) j = (i / q.srow[y]) * q.drow[y] + (i % q.srow[y]);
        if (q.dstf[y]) q.dstf[y][j] = ov;
        if (q.dstb[y]) q.dstb[y][j] = __float2bfloat16(ov);
    }
}

__global__ void build_masks(const float* __restrict__ Wr, const float* __restrict__ thr,
                            unsigned* __restrict__ pm, unsigned* __restrict__ nm) {
    int r = blockIdx.x * 4 + (threadIdx.x >> 6);
    int w = threadIdx.x & 63;
    float t = thr[8];
    const float4* row = (const float4*)(Wr + (size_t)r * R_ + w * 32);
    unsigned p = 0u, ng = 0u;
    #pragma unroll
    for (int i4 = 0; i4 < 8; i4++) {
        float4 v4 = row[i4];
        float vv[4] = {v4.x, v4.y, v4.z, v4.w};
        #pragma unroll
        for (int j = 0; j < 4; j++) {
            float v = vv[j];
            if (fabsf(v) > t) {
                if (v > 0.f) p |= (1u << (i4 * 4 + j)); else ng |= (1u << (i4 * 4 + j));
            }
        }
    }
    pm[w * R_ + r] = p;
    nm[w * R_ + r] = ng;
}

// ---------------- epilogue -----------------------------------------------
template<int EPI>
__device__ __forceinline__ float epi_f(float v, const float* bias, const float* extra,
                                       int gm, int gn, int lde) {
    if (bias) v = __fadd_rn(v, bias[gn]);
    if (EPI == 1) v = 0.5f * v * (1.0f + erff(v * 0.70710678118654752f));
    else if (EPI == 2) v = v / (1.0f + expf(-v));
    else if (EPI == 3) v = v * extra[(size_t)gm * lde + gn];
    else if (EPI == 4) v = __fadd_rn(extra[(size_t)gm * lde + gn], v);
    return v;
}

// ---------------- mma.sync / cp.async helpers -----------------------------
__device__ __forceinline__ uint32_t smem_u32(const void* p) {
    uint32_t a;
    asm("{ .reg .u64 t; cvta.to.shared.u64 t, %1; cvt.u32.u64 %0, t; }" : "=r"(a) : "l"(p));
    return a;
}
__device__ __forceinline__ void ldm_x4(uint32_t& a0, uint32_t& a1, uint32_t& a2, uint32_t& a3,
                                       uint32_t addr) {
    asm volatile("ldmatrix.sync.aligned.m8n8.x4.shared.b16 {%0,%1,%2,%3}, [%4];"
                 : "=r"(a0), "=r"(a1), "=r"(a2), "=r"(a3) : "r"(addr));
}
__device__ __forceinline__ void ldm_x2(uint32_t& b0, uint32_t& b1, uint32_t addr) {
    asm volatile("ldmatrix.sync.aligned.m8n8.x2.shared.b16 {%0,%1}, [%2];"
                 : "=r"(b0), "=r"(b1) : "r"(addr));
}
__device__ __forceinline__ void mma_bf16(float* d, const uint32_t* a, const uint32_t* b) {
    asm volatile("mma.sync.aligned.m16n8k16.row.col.f32.bf16.bf16.f32 "
                 "{%0,%1,%2,%3}, {%4,%5,%6,%7}, {%8,%9}, {%0,%1,%2,%3};"
                 : "+f"(d[0]), "+f"(d[1]), "+f"(d[2]), "+f"(d[3])
                 : "r"(a[0]), "r"(a[1]), "r"(a[2]), "r"(a[3]), "r"(b[0]), "r"(b[1]));
}
__device__ __forceinline__ void cpa16(uint32_t dst, const void* src) {
    asm volatile("cp.async.cg.shared.global [%0], [%1], 16;" :: "r"(dst), "l"(src));
}
#define CPA_COMMIT() asm volatile("cp.async.commit_group;" ::: "memory")
#define CPA_WAIT1()  asm volatile("cp.async.wait_group 1;" ::: "memory")
#define CPA_WAIT0()  asm volatile("cp.async.wait_group 0;" ::: "memory")

#define PITCH 40    // bf16 per smem row (80B, 16B-aligned, ldmatrix conflict-free)
#define BUFB  10240 // bytes per operand buffer (128 rows * 80B)

// ---------------- HMMA GEMM, pre-split A, cp.async 2-stage (R14-proven) ---
template<int EPI, bool HLOUT>
__global__ void __launch_bounds__(256)
gemm_bb(const bf16* __restrict__ Ah, const bf16* __restrict__ Al,
        const bf16* __restrict__ Bb,
        const float* __restrict__ bias, const float* __restrict__ extra,
        float* __restrict__ C, bf16* __restrict__ Ch, bf16* __restrict__ Cl,
        int K, int lda, int ldb, int ldc, int lde)
{
    extern __shared__ __align__(16) char dsm[];
    const uint32_t sb = smem_u32(dsm);

    const int tid = threadIdx.x, wid = tid >> 5, lane = tid & 31;
    const int row0 = blockIdx.y * 128, col0 = blockIdx.x * 128;
    const int wm = (wid >> 2) * 64, wn = (wid & 3) * 32;
    const int lrow = tid >> 1, lhalf = tid & 1;
    const int NC = K >> 5;

    float acc[4][4][4];
    #pragma unroll
    for (int i = 0; i < 4; i++)
        #pragma unroll
        for (int j = 0; j < 4; j++)
            #pragma unroll
            for (int c = 0; c < 4; c++) acc[i][j][c] = 0.f;

    auto prefetch = [&](int c, int s) {
        int kt = c << 5;
        uint32_t doff = sb + s * (3 * BUFB) + (uint32_t)lrow * 80 + lhalf * 32;
        const bf16* ga = Ah + (size_t)(row0 + lrow) * lda + kt + lhalf * 16;
        const bf16* gl = Al + (size_t)(row0 + lrow) * lda + kt + lhalf * 16;
        const bf16* gb = Bb + (size_t)(col0 + lrow) * ldb + kt + lhalf * 16;
        cpa16(doff,                ga);     cpa16(doff + 16,            ga + 8);
        cpa16(doff + BUFB,         gl);     cpa16(doff + BUFB + 16,     gl + 8);
        cpa16(doff + 2 * BUFB,     gb);     cpa16(doff + 2 * BUFB + 16, gb + 8);
        CPA_COMMIT();
    };

    prefetch(0, 0);
    for (int c = 0; c < NC; c++) {
        if (c + 1 < NC) prefetch(c + 1, (c + 1) & 1);
        if (c + 1 < NC) CPA_WAIT1(); else CPA_WAIT0();
        __syncthreads();

        const uint32_t sAhi = sb + (c & 1) * (3 * BUFB);
        const uint32_t sAlo = sAhi + BUFB;
        const uint32_t sBs  = sAhi + 2 * BUFB;

        #pragma unroll
        for (int ks = 0; ks < 32; ks += 16) {
            uint32_t afh[4][4], afl[4][4], bf[4][2];
            int ar = lane & 15, ac = (lane >> 4) * 8;
            #pragma unroll
            for (int i = 0; i < 4; i++) {
                uint32_t off = (uint32_t)(wm + i * 16 + ar) * (PITCH * 2) + (ks + ac) * 2;
                ldm_x4(afh[i][0], afh[i][1], afh[i][2], afh[i][3], sAhi + off);
                ldm_x4(afl[i][0], afl[i][1], afl[i][2], afl[i][3], sAlo + off);
            }
            int br = lane & 7, bm = (lane >> 3) & 1;
            #pragma unroll
            for (int j = 0; j < 4; j++) {
                uint32_t off = (uint32_t)(wn + j * 8 + br) * (PITCH * 2) + (ks + bm * 8) * 2;
                ldm_x2(bf[j][0], bf[j][1], sBs + off);
            }
            #pragma unroll
            for (int i = 0; i < 4; i++)
                #pragma unroll
                for (int j = 0; j < 4; j++) {
                    mma_bf16(acc[i][j], afh[i], bf[j]);
                    mma_bf16(acc[i][j], afl[i], bf[j]);
                }
        }
        __syncthreads();
    }

    const int gr = lane >> 2, gc = (lane & 3) * 2;
    #pragma unroll
    for (int i = 0; i < 4; i++) {
        #pragma unroll
        for (int j = 0; j < 4; j++) {
            int gm0 = row0 + wm + i * 16 + gr;
            int gm1 = gm0 + 8;
            int gn  = col0 + wn + j * 8 + gc;
            float v00 = epi_f<EPI>(acc[i][j][0], bias, extra, gm0, gn,     lde);
            float v01 = epi_f<EPI>(acc[i][j][1], bias, extra, gm0, gn + 1, lde);
            float v10 = epi_f<EPI>(acc[i][j][2], bias, extra, gm1, gn,     lde);
            float v11 = epi_f<EPI>(acc[i][j][3], bias, extra, gm1, gn + 1, lde);
            if (HLOUT) {
                bf16 h;
                h = __float2bfloat16(v00); Ch[(size_t)gm0 * ldc + gn]     = h; Cl[(size_t)gm0 * ldc + gn]     = __float2bfloat16(v00 - __bfloat162float(h));
                h = __float2bfloat16(v01); Ch[(size_t)gm0 * ldc + gn + 1] = h; Cl[(size_t)gm0 * ldc + gn + 1] = __float2bfloat16(v01 - __bfloat162float(h));
                h = __float2bfloat16(v10); Ch[(size_t)gm1 * ldc + gn]     = h; Cl[(size_t)gm1 * ldc + gn]     = __float2bfloat16(v10 - __bfloat162float(h));
                h = __float2bfloat16(v11); Ch[(size_t)gm1 * ldc + gn + 1] = h; Cl[(size_t)gm1 * ldc + gn + 1] = __float2bfloat16(v11 - __bfloat162float(h));
            } else {
                C[(size_t)gm0 * ldc + gn]     = v00;
                C[(size_t)gm0 * ldc + gn + 1] = v01;
                C[(size_t)gm1 * ldc + gn]     = v10;
                C[(size_t)gm1 * ldc + gn + 1] = v11;
            }
        }
    }
}

// ---------------- attention scores on pre-split qkv: sc = (q k^T)/8 -------
__global__ void __launch_bounds__(256)
gemm_qk(const bf16* __restrict__ qh, const bf16* __restrict__ ql, float* __restrict__ sc)
{
    __shared__ __align__(16) bf16 Ahi[128 * PITCH];
    __shared__ __align__(16) bf16 Alo[128 * PITCH];
    __shared__ __align__(16) bf16 Bhi[128 * PITCH];
    __shared__ __align__(16) bf16 Blo[128 * PITCH];

    const int tid = threadIdx.x, wid = tid >> 5, lane = tid & 31;
    const int z = blockIdx.z;
    const size_t aoff = (size_t)(z >> 3) * T_ * 1536 + (z & 7) * 64;
    const size_t boff = aoff + 512;
    float* C = sc + (size_t)z * T_ * T_;
    const int row0 = blockIdx.y * 128, col0 = blockIdx.x * 128;
    const int wm = (wid >> 2) * 64, wn = (wid & 3) * 32;
    const uint32_t sAh = smem_u32(Ahi), sAl = smem_u32(Alo);
    const uint32_t sBh = smem_u32(Bhi), sBl = smem_u32(Blo);
    const int lrow = tid >> 1, lhalf = tid & 1;

    float acc[4][4][4];
    #pragma unroll
    for (int i = 0; i < 4; i++)
        #pragma unroll
        for (int j = 0; j < 4; j++)
            #pragma unroll
            for (int c = 0; c < 4; c++) acc[i][j][c] = 0.f;

    #pragma unroll
    for (int kt = 0; kt < 64; kt += 32) {
        {
            size_t ai = aoff + (size_t)(row0 + lrow) * 1536 + kt + lhalf * 16;
            size_t bi = boff + (size_t)(col0 + lrow) * 1536 + kt + lhalf * 16;
            uint4* d;
            d = (uint4*)(Ahi + lrow * PITCH + lhalf * 16);
            d[0] = ((const uint4*)(qh + ai))[0]; d[1] = ((const uint4*)(qh + ai))[1];
            d = (uint4*)(Alo + lrow * PITCH + lhalf * 16);
            d[0] = ((const uint4*)(ql + ai))[0]; d[1] = ((const uint4*)(ql + ai))[1];
            d = (uint4*)(Bhi + lrow * PITCH + lhalf * 16);
            d[0] = ((const uint4*)(qh + bi))[0]; d[1] = ((const uint4*)(qh + bi))[1];
            d = (uint4*)(Blo + lrow * PITCH + lhalf * 16);
            d[0] = ((const uint4*)(ql + bi))[0]; d[1] = ((const uint4*)(ql + bi))[1];
        }
        __syncthreads();
        #pragma unroll
        for (int ks = 0; ks < 32; ks += 16) {
            uint32_t afh[4][4], afl[4][4], bfh[4][2], bfl[4][2];
            int ar = lane & 15, ac = (lane >> 4) * 8;
            #pragma unroll
            for (int i = 0; i < 4; i++) {
                uint32_t off = (uint32_t)(wm + i * 16 + ar) * (PITCH * 2) + (ks + ac) * 2;
                ldm_x4(afh[i][0], afh[i][1], afh[i][2], afh[i][3], sAh + off);
                ldm_x4(afl[i][0], afl[i][1], afl[i][2], afl[i][3], sAl + off);
            }
            int br = lane & 7, bm = (lane >> 3) & 1;
            #pragma unroll
            for (int j = 0; j < 4; j++) {
                uint32_t off = (uint32_t)(wn + j * 8 + br) * (PITCH * 2) + (ks + bm * 8) * 2;
                ldm_x2(bfh[j][0], bfh[j][1], sBh + off);
                ldm_x2(bfl[j][0], bfl[j][1], sBl + off);
            }
            #pragma unroll
            for (int i = 0; i < 4; i++)
                #pragma unroll
                for (int j = 0; j < 4; j++) {
                    mma_bf16(acc[i][j], afh[i], bfh[j]);
                    mma_bf16(acc[i][j], afh[i], bfl[j]);
                    mma_bf16(acc[i][j], afl[i], bfh[j]);
                }
        }
        __syncthreads();
    }

    const int gr = lane >> 2, gc = (lane & 3) * 2;
    #pragma unroll
    for (int i = 0; i < 4; i++) {
        #pragma unroll
        for (int j = 0; j < 4; j++) {
            int gm0 = row0 + wm + i * 16 + gr;
            int gm1 = gm0 + 8;
            int gn  = col0 + wn + j * 8 + gc;
            C[(size_t)gm0 * T_ + gn]     = acc[i][j][0] * 0.125f;
            C[(size_t)gm0 * T_ + gn + 1] = acc[i][j][1] * 0.125f;
            C[(size_t)gm1 * T_ + gn]     = acc[i][j][2] * 0.125f;
            C[(size_t)gm1 * T_ + gn + 1] = acc[i][j][3] * 0.125f;
        }
    }
}

// ---------------- v transpose on pre-split qkv: vt[z][d][t] ---------------
__global__ void transpose_v(const bf16* __restrict__ qh, const bf16* __restrict__ ql,
                            bf16* __restrict__ vth, bf16* __restrict__ vtl) {
    __shared__ uint32_t tile[32][33];
    const int z = blockIdx.z;
    const size_t s = (size_t)(z >> 3) * T_ * 1536 + 1024 + (z & 7) * 64;
    const int tbase = blockIdx.x * 32, dbase = blockIdx.y * 32;
    const int tx = threadIdx.x & 31, ty = threadIdx.x >> 5;
    #pragma unroll
    for (int l = 0; l < 4; l++) {
        size_t ix = s + (size_t)(tbase + ty + l * 8) * 1536 + dbase + tx;
        tile[tx][ty + l * 8] = (uint32_t)__bfloat16_as_ushort(qh[ix]) |
                               ((uint32_t)__bfloat16_as_ushort(ql[ix]) << 16);
    }
    __syncthreads();
    #pragma unroll
    for (int l = 0; l < 4; l++) {
        size_t ox = (size_t)z * 64 * T_ + (size_t)(dbase + ty + l * 8) * T_ + tbase + tx;
        uint32_t v = tile[ty + l * 8][tx];
        vth[ox] = __ushort_as_bfloat16((unsigned short)(v & 0xFFFF));
        vtl[ox] = __ushort_as_bfloat16((unsigned short)(v >> 16));
    }
}

// ---------------- attention output on pre-split: o = attn @ v (hl out) ----
__global__ void __launch_bounds__(256)
gemm_ov(const bf16* __restrict__ ph, const bf16* __restrict__ pl,
        const bf16* __restrict__ vth, const bf16* __restrict__ vtl,
        bf16* __restrict__ oh, bf16* __restrict__ ol)
{
    __shared__ __align__(16) bf16 Ahi[128 * PITCH];
    __shared__ __align__(16) bf16 Alo[128 * PITCH];
    __shared__ __align__(16) bf16 Bhi[64 * PITCH];
    __shared__ __align__(16) bf16 Blo[64 * PITCH];

    const int tid = threadIdx.x, wid = tid >> 5, lane = tid & 31;
    const int z = blockIdx.y;
    const bf16* Ahp = ph + (size_t)z * T_ * T_;
    const bf16* Alp = pl + (size_t)z * T_ * T_;
    const bf16* Bhp = vth + (size_t)z * 64 * T_;
    const bf16* Blp = vtl + (size_t)z * 64 * T_;
    const size_t coff = (size_t)(z >> 3) * T_ * DIM_ + (z & 7) * 64;
    const int row0 = blockIdx.x * 128;
    const int wm = (wid >> 2) * 64, wn = (wid & 3) * 16;
    const uint32_t sAh = smem_u32(Ahi), sAl = smem_u32(Alo);
    const uint32_t sBh = smem_u32(Bhi), sBl = smem_u32(Blo);
    const int lrow = tid >> 1, lhalf = tid & 1;

    float acc[4][2][4];
    #pragma unroll
    for (int i = 0; i < 4; i++)
        #pragma unroll
        for (int j = 0; j < 2; j++)
            #pragma unroll
            for (int c = 0; c < 4; c++) acc[i][j][c] = 0.f;

    for (int kt = 0; kt < T_; kt += 32) {
        {
            size_t ai = (size_t)(row0 + lrow) * T_ + kt + lhalf * 16;
            uint4* d;
            d = (uint4*)(Ahi + lrow * PITCH + lhalf * 16);
            d[0] = ((const uint4*)(Ahp + ai))[0]; d[1] = ((const uint4*)(Ahp + ai))[1];
            d = (uint4*)(Alo + lrow * PITCH + lhalf * 16);
            d[0] = ((const uint4*)(Alp + ai))[0]; d[1] = ((const uint4*)(Alp + ai))[1];
            if (tid < 128) {
                size_t bi = (size_t)lrow * T_ + kt + lhalf * 16;
                d = (uint4*)(Bhi + lrow * PITCH + lhalf * 16);
                d[0] = ((const uint4*)(Bhp + bi))[0]; d[1] = ((const uint4*)(Bhp + bi))[1];
                d = (uint4*)(Blo + lrow * PITCH + lhalf * 16);
                d[0] = ((const uint4*)(Blp + bi))[0]; d[1] = ((const uint4*)(Blp + bi))[1];
            }
        }
        __syncthreads();
        #pragma unroll
        for (int ks = 0; ks < 32; ks += 16) {
            uint32_t afh[4][4], afl[4][4], bfh[2][2], bfl[2][2];
            int ar = lane & 15, ac = (lane >> 4) * 8;
            #pragma unroll
            for (int i = 0; i < 4; i++) {
                uint32_t off = (uint32_t)(wm + i * 16 + ar) * (PITCH * 2) + (ks + ac) * 2;
                ldm_x4(afh[i][0], afh[i][1], afh[i][2], afh[i][3], sAh + off);
                ldm_x4(afl[i][0], afl[i][1], afl[i][2], afl[i][3], sAl + off);
            }
            int br = lane & 7, bm = (lane >> 3) & 1;
            #pragma unroll
            for (int j = 0; j < 2; j++) {
                uint32_t off = (uint32_t)(wn + j * 8 + br) * (PITCH * 2) + (ks + bm * 8) * 2;
                ldm_x2(bfh[j][0], bfh[j][1], sBh + off);
                ldm_x2(bfl[j][0], bfl[j][1], sBl + off);
            }
            #pragma unroll
            for (int i = 0; i < 4; i++)
                #pragma unroll
                for (int j = 0; j < 2; j++) {
                    mma_bf16(acc[i][j], afh[i], bfh[j]);
                    mma_bf16(acc[i][j], afh[i], bfl[j]);
                    mma_bf16(acc[i][j], afl[i], bfh[j]);
                }
        }
        __syncthreads();
    }

    const int gr = lane >> 2, gc = (lane & 3) * 2;
    #pragma unroll
    for (int i = 0; i < 4; i++) {
        #pragma unroll
        for (int j = 0; j < 2; j++) {
            int gm0 = row0 + wm + i * 16 + gr;
            int gm1 = gm0 + 8;
            int gn  = wn + j * 8 + gc;
            float v; bf16 h;
            v = acc[i][j][0]; h = __float2bfloat16(v);
            oh[coff + (size_t)gm0 * DIM_ + gn] = h;     ol[coff + (size_t)gm0 * DIM_ + gn] = __float2bfloat16(v - __bfloat162float(h));
            v = acc[i][j][1]; h = __float2bfloat16(v);
            oh[coff + (size_t)gm0 * DIM_ + gn + 1] = h; ol[coff + (size_t)gm0 * DIM_ + gn + 1] = __float2bfloat16(v - __bfloat162float(h));
            v = acc[i][j][2]; h = __float2bfloat16(v);
            oh[coff + (size_t)gm1 * DIM_ + gn] = h;     ol[coff + (size_t)gm1 * DIM_ + gn] = __float2bfloat16(v - __bfloat162float(h));
            v = acc[i][j][3]; h = __float2bfloat16(v);
            oh[coff + (size_t)gm1 * DIM_ + gn + 1] = h; ol[coff + (size_t)gm1 * DIM_ + gn + 1] = __float2bfloat16(v - __bfloat162float(h));
        }
    }
}

// ---------------- FAST fp32 SGEMM (xp only; bit-exact, unchanged) --------
template<int EPI, bool TB>
__global__ void __launch_bounds__(256)
gemm_fast(const float* __restrict__ A, const float* __restrict__ Bm,
          const float* __restrict__ bias, const float* __restrict__ extra,
          float* __restrict__ C,
          int M, int N, int K, int lda, int ldb, int ldc, int lde,
          long aZ1, long aZ2, long bZ1, long bZ2, long cZ1, long cZ2,
          int zInner, float alpha)
{
    int z = blockIdx.z;
    int zo = z / zInner, zi = z - zo * zInner;
    A  += zo * aZ1 + zi * aZ2;
    Bm += zo * bZ1 + zi * bZ2;
    C  += zo * cZ1 + zi * cZ2;

    __shared__ float As[16][132];
    __shared__ float Bs[16][132];
    const int tid = threadIdx.x;
    const int row0 = blockIdx.y * 128, col0 = blockIdx.x * 128;
    const int ty = tid >> 4, tx = tid & 15;
    const int KT = K >> 4;

    const int am = (tid >> 2), ak = (tid & 3) << 2;
    const int bk = (tid >> 5), bn = (tid & 31) << 2;

    float4 ra[2], rb[2];
    float acc[8][8];
    #pragma unroll
    for (int i = 0; i < 8; i++)
        #pragma unroll
        for (int j = 0; j < 8; j++) acc[i][j] = 0.f;

    auto ldg = [&](int kt0) {
        #pragma unroll
        for (int l = 0; l < 2; l++)
            ra[l] = *(const float4*)(A + (size_t)(row0 + am + l * 64) * lda + kt0 + ak);
        if (TB) {
            #pragma unroll
            for (int l = 0; l < 2; l++)
                rb[l] = *(const float4*)(Bm + (size_t)(col0 + am + l * 64) * ldb + kt0 + ak);
        } else {
            #pragma unroll
            for (int l = 0; l < 2; l++)
                rb[l] = *(const float4*)(Bm + (size_t)(kt0 + bk + l * 8) * ldb + col0 + bn);
        }
    };
    auto sts = [&]() {
        #pragma unroll
        for (int l = 0; l < 2; l++) {
            As[ak + 0][am + l * 64] = ra[l].x;
            As[ak + 1][am + l * 64] = ra[l].y;
            As[ak + 2][am + l * 64] = ra[l].z;
            As[ak + 3][am + l * 64] = ra[l].w;
        }
        if (TB) {
            #pragma unroll
            for (int l = 0; l < 2; l++) {
                Bs[ak + 0][am + l * 64] = rb[l].x;
                Bs[ak + 1][am + l * 64] = rb[l].y;
                Bs[ak + 2][am + l * 64] = rb[l].z;
                Bs[ak + 3][am + l * 64] = rb[l].w;
            }
        } else {
            #pragma unroll
            for (int l = 0; l < 2; l++)
                *(float4*)&Bs[bk + l * 8][bn] = rb[l];
        }
    };

    ldg(0); sts(); __syncthreads();
    for (int kt = 1; kt <= KT; kt++) {
        if (kt < KT) ldg(kt << 4);
        #pragma unroll
        for (int k = 0; k < 16; k++) {
            float4 a0 = *(const float4*)&As[k][ty * 8];
            float4 a1 = *(const float4*)&As[k][ty * 8 + 4];
            float4 b0 = *(const float4*)&Bs[k][tx * 8];
            float4 b1 = *(const float4*)&Bs[k][tx * 8 + 4];
            float av[8] = {a0.x, a0.y, a0.z, a0.w, a1.x, a1.y, a1.z, a1.w};
            float bv[8] = {b0.x, b0.y, b0.z, b0.w, b1.x, b1.y, b1.z, b1.w};
            #pragma unroll
            for (int i = 0; i < 8; i++)
                #pragma unroll
                for (int j = 0; j < 8; j++) acc[i][j] += av[i] * bv[j];
        }
        __syncthreads();
        if (kt < KT) { sts(); __syncthreads(); }
    }

    #pragma unroll
    for (int i = 0; i < 8; i++) {
        int gm = row0 + ty * 8 + i;
        #pragma unroll
        for (int j = 0; j < 8; j++) {
            int gn = col0 + tx * 8 + j;
            float v = epi_f<EPI>(acc[i][j] * alpha, bias, extra, gm, gn, lde);
            C[(size_t)gm * ldc + gn] = v;
        }
    }
}

// ---------------- LIF scan (R14-proven original) --------------------------
__global__ void __cluster_dims__(8, 1, 1) __launch_bounds__(256, 1)
scan_kernel(const float* __restrict__ xp,
            const float* __restrict__ beta, const float* __restrict__ sfa_inc,
            const float* __restrict__ sfa_decay,
            const unsigned* __restrict__ pmask, const unsigned* __restrict__ nmask,
            float* __restrict__ acts)
{
    cg::cluster_group cl = cg::this_cluster();
    int crank = (int)cl.block_rank();
    int b = blockIdx.x >> 3;
    int tid = threadIdx.x;
    int r = crank * 256 + tid;
    int lane = tid & 31;
    int gw = r >> 5;

    __shared__ unsigned s_spk[2][64];
    if (tid < 64) { s_spk[0][tid] = 0u; s_spk[1][tid] = 0u; }

    unsigned pm[64], nm[64];
    #pragma unroll
    for (int w = 0; w < 64; w++) { pm[w] = pmask[w * R_ + r]; nm[w] = nmask[w * R_ + r]; }

    float beta_r = beta[r], dec = sfa_decay[r], inc = sfa_inc[r];
    float mem = 0.f, ath = 0.f;
    const float* __restrict__ xrow = xp + (size_t)b * T_ * R_ + r;
    float* __restrict__ arow = acts + (size_t)b * T_ * R_ + r;

    cl.sync();

    for (int t = 0; t < T_; t++) {
        int pb = t & 1, wb = pb ^ 1;
        int acc = 0;
        #pragma unroll
        for (int w = 0; w < 64; w++) {
            unsigned s = s_spk[pb][w];
            acc += __popc(pm[w] & s);
            acc -= __popc(nm[w] & s);
        }
        float cur = __fadd_rn(xrow[(size_t)t * R_], (float)acc);
        mem = __fadd_rn(__fmul_rn(beta_r, mem), cur);
        float th = __fadd_rn(1.0f, ath);
        bool sp = __fsub_rn(mem, th) > 0.0f;
        float spk = sp ? 1.0f : 0.0f;
        if (sp) mem = 0.0f;
        ath = __fadd_rn(__fmul_rn(dec, ath), __fmul_rn(inc, spk));
        arow[(size_t)t * R_] = spk;

        unsigned bal = __ballot_sync(0xffffffffu, sp);
        if (lane == 0) {
            #pragma unroll
            for (int dst = 0; dst < 8; dst++) {
                unsigned* rp = (unsigned*)cl.map_shared_rank(&s_spk[wb][gw], dst);
                *rp = bal;
            }
        }
        cl.sync();
    }
}

// ---------------- rmsnorm -> pre-split hi/lo ------------------------------
__global__ void rmsnorm_hl(const float* __restrict__ x, const float* __restrict__ w,
                           bf16* __restrict__ oh, bf16* __restrict__ ol, int N) {
    int row = blockIdx.x;
    const float* xr = x + (size_t)row * N;
    __shared__ float sm[256];
    __shared__ float s_scale;
    float acc = 0.f;
    for (int i = threadIdx.x; i < N; i += 256) { float v = xr[i]; acc += v * v; }
    sm[threadIdx.x] = acc; __syncthreads();
    for (int s = 128; s > 0; s >>= 1) {
        if (threadIdx.x < s) sm[threadIdx.x] += sm[threadIdx.x + s];
        __syncthreads();
    }
    if (threadIdx.x == 0)
        s_scale = rsqrtf(__fadd_rn(__fdiv_rn(sm[0], (float)N), 1e-6f));
    __syncthreads();
    float sc = s_scale;
    for (int i = threadIdx.x; i < N; i += 256) {
        float v = __fmul_rn(__fmul_rn(xr[i], sc), w[i]);
        size_t ix = (size_t)row * N + i;
        bf16 h = __float2bfloat16(v);
        oh[ix] = h;
        ol[ix] = __float2bfloat16(v - __bfloat162float(h));
    }
}

// ---------------- softmax -> pre-split probs ------------------------------
__global__ void softmax_k(const float* __restrict__ s, bf16* __restrict__ ph,
                          bf16* __restrict__ pl) {
    int row = blockIdx.x;
    const float* p = s + (size_t)row * 512;
    __shared__ float sm[128];
    int tid = threadIdx.x;
    float m = -3.402823466e38f;
    #pragma unroll
    for (int l = 0; l < 4; l++) m = fmaxf(m, p[tid + l * 128]);
    sm[tid] = m; __syncthreads();
    for (int st = 64; st > 0; st >>= 1) {
        if (tid < st) sm[tid] = fmaxf(sm[tid], sm[tid + st]);
        __syncthreads();
    }
    float M = sm[0]; __syncthreads();
    float e[4]; float acc = 0.f;
    #pragma unroll
    for (int l = 0; l < 4; l++) { e[l] = expf(p[tid + l * 128] - M); acc += e[l]; }
    sm[tid] = acc; __syncthreads();
    for (int st = 64; st > 0; st >>= 1) {
        if (tid < st) sm[tid] += sm[tid + st];
        __syncthreads();
    }
    float sum = sm[0];
    #pragma unroll
    for (int l = 0; l < 4; l++) {
        float v = __fdiv_rn(e[l], sum);
        size_t ix = (size_t)row * 512 + tid + l * 128;
        bf16 h = __float2bfloat16(v);
        ph[ix] = h;
        pl[ix] = __float2bfloat16(v - __bfloat162float(h));
    }
}

// ---------------- host ---------------------------------------------------
template<typename T> static T* devptr(const void* sym) {
    void* p = nullptr; cudaGetSymbolAddress(&p, sym); return (T*)p;
}

#define GB_SMEM (6 * BUFB)   // 61440 bytes, 2-stage (R14-proven)

template<int EPI>
static void GB(const bf16* Ah, const bf16* Al, const bf16* Bb, const float* bias,
               const float* extra, float* C,
               int M, int N, int K, int lda, int ldb, int ldc, int lde) {
    cudaFuncSetAttribute(gemm_bb<EPI, false>, cudaFuncAttributeMaxDynamicSharedMemorySize, GB_SMEM);
    dim3 grid(N / 128, M / 128);
    gemm_bb<EPI, false><<<grid, 256, GB_SMEM>>>(Ah, Al, Bb, bias, extra, C, nullptr, nullptr,
                                                K, lda, ldb, ldc, lde);
}

template<int EPI>
static void GBH(const bf16* Ah, const bf16* Al, const bf16* Bb, const float* bias,
                const float* extra, bf16* Ch, bf16* Cl,
                int M, int N, int K, int lda, int ldb, int ldc, int lde) {
    cudaFuncSetAttribute(gemm_bb<EPI, true>, cudaFuncAttributeMaxDynamicSharedMemorySize, GB_SMEM);
    dim3 grid(N / 128, M / 128);
    gemm_bb<EPI, true><<<grid, 256, GB_SMEM>>>(Ah, Al, Bb, bias, extra, nullptr, Ch, Cl,
                                               K, lda, ldb, ldc, lde);
}

template<int EPI, bool TB>
static void GF(const float* A, const float* Bm, const float* bias, const float* extra, float* C,
               int M, int N, int K, int lda, int ldb, int ldc, int lde,
               long aZ1, long aZ2, long bZ1, long bZ2, long cZ1, long cZ2,
               int zInner, int Z, float alpha) {
    dim3 grid(N / 128, M / 128, Z);
    gemm_fast<EPI, TB><<<grid, 256>>>(A, Bm, bias, extra, C, M, N, K, lda, ldb, ldc, lde,
                                      aZ1, aZ2, bZ1, bZ2, cZ1, cZ2, zInner, alpha);
}

extern "C" void kernel_launch(void* const* d_in, const int* in_sizes, int n_in,
                              void* d_out, int out_size) {
    const float* x        = (const float*)d_in[0];
    const float* Wi       = (const float*)d_in[1];
    const float* bi       = (const float*)d_in[2];
    const float* Wr       = (const float*)d_in[3];
    const float* rn_w     = (const float*)d_in[4];
    const float* W1       = (const float*)d_in[5];
    const float* b1       = (const float*)d_in[6];
    const float* W2       = (const float*)d_in[7];
    const float* b2       = (const float*)d_in[8];
    const float* anorm_w  = (const float*)d_in[9];
    const float* Wqkv     = (const float*)d_in[10];
    const float* Wo       = (const float*)d_in[11];
    const float* fnorm_w  = (const float*)d_in[12];
    const float* Wf1      = (const float*)d_in[13];
    const float* Wf2      = (const float*)d_in[14];
    const float* Wf3      = (const float*)d_in[15];
    const float* beta     = (const float*)d_in[16];
    const float* sfa_inc  = (const float*)d_in[17];
    const float* sfa_dec  = (const float*)d_in[18];
    float* out = (float*)d_out;
    const int FFH = in_sizes[13] / DIM_;

    float* red    = devptr<float>(g_red);
    float* thr    = devptr<float>(g_thr);
    float* qWi    = devptr<float>(g_qWi);
    bf16* bW1   = devptr<bf16>(g_bW1);
    bf16* bW2   = devptr<bf16>(g_bW2);
    bf16* bWqkv = devptr<bf16>(g_bWqkv);
    bf16* bWo   = devptr<bf16>(g_bWo);
    bf16* bWf1  = devptr<bf16>(g_bWf1);
    bf16* bWf2p = devptr<bf16>(g_bWf2p);
    bf16* bWf3  = devptr<bf16>(g_bWf3);
    unsigned* pm  = devptr<unsigned>(g_pm);
    unsigned* nm  = devptr<unsigned>(g_nm);
    float* xp     = devptr<float>(g_xp);
    float* acts   = devptr<float>(g_acts);
    float* y      = devptr<float>(g_y);
    float* sc     = devptr<float>(g_sc);
    float* xres   = devptr<float>(g_xres);
    float* gbuf   = devptr<float>(g_g);
    bf16 *hnh = devptr<bf16>(g_hnh), *hnl = devptr<bf16>(g_hnl);
    bf16 *hh  = devptr<bf16>(g_hh),  *hl  = devptr<bf16>(g_hl2);
    bf16 *xah = devptr<bf16>(g_xah), *xal = devptr<bf16>(g_xal);
    bf16 *qkvh= devptr<bf16>(g_qkvh),*qkvl= devptr<bf16>(g_qkvl);
    bf16 *sph = devptr<bf16>(g_sph), *spl = devptr<bf16>(g_spl);
    bf16 *vth = devptr<bf16>(g_vth), *vtl = devptr<bf16>(g_vtl);
    bf16 *oh  = devptr<bf16>(g_oh),  *ol  = devptr<bf16>(g_ol);
    bf16 *xfh = devptr<bf16>(g_xfh), *xfl = devptr<bf16>(g_xfl);
    bf16 *guh = devptr<bf16>(g_guh), *gul = devptr<bf16>(g_gul);

    // batched quantization (bit-identical per-tensor reduction order)
    Q9 q;
    for (int i = 0; i < 9; i++) { q.dstf[i] = nullptr; q.dstb[i] = nullptr; q.srow[i] = 1; q.drow[i] = 1; }
    q.src[0] = Wi;   q.dstf[0] = qWi;   q.n[0] = R_ * DIM_;
    q.src[1] = W1;   q.dstb[1] = bW1;   q.n[1] = 2 * DIM_ * R_;
    q.src[2] = W2;   q.dstb[2] = bW2;   q.n[2] = DIM_ * 2 * DIM_;
    q.src[3] = Wqkv; q.dstb[3] = bWqkv; q.n[3] = 3 * DIM_ * DIM_;
    q.src[4] = Wo;   q.dstb[4] = bWo;   q.n[4] = DIM_ * DIM_;
    q.src[5] = Wf1;  q.dstb[5] = bWf1;  q.n[5] = FFH * DIM_;
    q.src[6] = Wf2;  q.dstb[6] = bWf2p; q.n[6] = DIM_ * FFH;  q.srow[6] = FFH; q.drow[6] = FFHP;
    q.src[7] = Wf3;  q.dstb[7] = bWf3;  q.n[7] = FFH * DIM_;
    q.src[8] = Wr;   q.n[8] = R_ * R_;

    absmean_partial_all<<<dim3(256, 9), 256>>>(q, red);
    absmean_final_all<<<9, 256>>>(red, q, thr);
    quantize_all<<<dim3((2 * DIM_ * R_ + 255) / 256, 8), 256>>>(q, thr);
    build_masks<<<R_ / 4, 256>>>(Wr, thr, pm, nm);

    // xp = x @ qWi^T + bi  (fp32 exact — feeds the chaotic spike threshold)
    GF<0, true>(x, qWi, bi, nullptr, xp, BT_, R_, DIM_, DIM_, DIM_, R_, 0,
                0, 0, 0, 0, 0, 0, 1, 1, 1.f);

    // LIF scan
    scan_kernel<<<64, 256>>>(xp, beta, sfa_inc, sfa_dec, pm, nm, acts);

    // readout MLP (pre-split HMMA + cp.async 2-stage pipeline)
    rmsnorm_hl<<<BT_, 256>>>(acts, rn_w, hnh, hnl, R_);
    GBH<1>(hnh, hnl, bW1, b1, nullptr, hh, hl, BT_, 2 * DIM_, R_, R_, R_, 2 * DIM_, 0);
    GB<0>(hh, hl, bW2, b2, nullptr, y, BT_, DIM_, 2 * DIM_, 2 * DIM_, 2 * DIM_, DIM_, 0);

    // attention block
    rmsnorm_hl<<<BT_, 256>>>(y, anorm_w, xah, xal, DIM_);
    GBH<0>(xah, xal, bWqkv, nullptr, nullptr, qkvh, qkvl, BT_, 3 * DIM_, DIM_, DIM_, DIM_, 3 * DIM_, 0);
    gemm_qk<<<dim3(4, 4, 64), 256>>>(qkvh, qkvl, sc);
    softmax_k<<<64 * T_, 128>>>(sc, sph, spl);
    transpose_v<<<dim3(16, 2, 64), 256>>>(qkvh, qkvl, vth, vtl);
    gemm_ov<<<dim3(4, 64), 256>>>(sph, spl, vth, vtl, oh, ol);
    // x_res = y + o @ Wo^T
    GB<4>(oh, ol, bWo, nullptr, y, xres, BT_, DIM_, DIM_, DIM_, DIM_, DIM_, DIM_);

    // SwiGLU FFN (padded to FFHP=1408, pads exact zero)
    rmsnorm_hl<<<BT_, 256>>>(xres, fnorm_w, xfh, xfl, DIM_);
    GB<2>(xfh, xfl, bWf1, nullptr, nullptr, gbuf, BT_, FFHP, DIM_, DIM_, DIM_, FFHP, 0);
    GBH<3>(xfh, xfl, bWf3, nullptr, gbuf, guh, gul, BT_, FFHP, DIM_, DIM_, DIM_, FFHP, FFHP);
    GB<4>(guh, gul, bWf2p, nullptr, xres, out, BT_, DIM_, FFHP, FFHP, FFHP, DIM_, DIM_);
}